// round 10
// baseline (speedup 1.0000x reference)
#include <cuda_runtime.h>

#define BB 512
#define TT 4096
#define IDIM 8
#define HH 64
#define GG 256
#define XCHUNK 256
#define NTHREADS 512

typedef unsigned long long ull;

// packed f32x2 FMA: d = a*b + c elementwise on two packed floats
static __device__ __forceinline__ ull dfma2(ull a, ull b, ull c) {
    ull d;
    asm("fma.rn.f32x2 %0, %1, %2, %3;" : "=l"(d) : "l"(a), "l"(b), "l"(c));
    return d;
}
static __device__ __forceinline__ float lo2(ull v) {
    return __int_as_float((int)(unsigned)(v & 0xffffffffull));
}
static __device__ __forceinline__ float hi2(ull v) {
    return __int_as_float((int)(unsigned)(v >> 32));
}

static __device__ __forceinline__ float sigf(float x) {
    return 1.0f / (1.0f + __expf(-x));
}
static __device__ __forceinline__ float tanh_f(float x) {
    float xc = fminf(fmaxf(x, -15.0f), 15.0f);
    float e = __expf(2.0f * xc);
    return 1.0f - 2.0f / (e + 1.0f);
}

static __device__ __forceinline__ void cp_async16(void* smem, const void* gmem) {
    unsigned saddr = (unsigned)__cvta_generic_to_shared(smem);
    asm volatile("cp.async.cg.shared.global [%0], [%1], 16;\n" :: "r"(saddr), "l"(gmem));
}

__global__ void __launch_bounds__(NTHREADS, 1)
lstm2_kernel(const float* __restrict__ x,
             const float* __restrict__ Wih0, const float* __restrict__ Whh0,
             const float* __restrict__ bih0, const float* __restrict__ bhh0,
             const float* __restrict__ Wih1, const float* __restrict__ Whh1,
             const float* __restrict__ bih1, const float* __restrict__ bhh1,
             const float* __restrict__ fcw, const float* __restrict__ fcb,
             float* __restrict__ out)
{
    const int b   = blockIdx.x;
    const int tid = threadIdx.x;
    const int g   = tid >> 1;       // gate index 0..255
    const int par = tid & 1;        // which half of the dot product
    const int gtype = g >> 6;       // 0:i 1:f 2:g 3:o  (warp-uniform)
    const int gj    = g & 63;       // state index within gate block

    __shared__ __align__(16) float xbuf[2][XCHUNK * IDIM];   // 2 x 8KB
    __shared__ __align__(16) float wih0s[GG * IDIM];         // 8KB, x-projection weights
    __shared__ __align__(16) float h0s[HH];
    __shared__ __align__(16) float h1s[HH];
    __shared__ __align__(16) float g0t[GG];   // transformed gates layer0, [j*4 + type]
    __shared__ __align__(16) float g1t[GG];   // transformed gates layer1

    // ---- weights into registers (~96 regs): pair-split ----
    // w1: even thread = Wih1 row g (acts on h0); odd = Whh1 row g (acts on h1)
    // w0: Whh0 row g, this thread's 32-dim half
    ull w1[HH / 2];   // 32 ull = 64 regs
    ull w0[HH / 4];   // 16 ull = 32 regs
    {
        const ull* p1 = (const ull*)((par ? Whh1 : Wih1) + g * HH);
#pragma unroll
        for (int i = 0; i < HH / 2; i++) w1[i] = p1[i];
        const ull* p0 = (const ull*)(Whh0 + g * HH + par * (HH / 2));
#pragma unroll
        for (int i = 0; i < HH / 4; i++) w0[i] = p0[i];
    }
    // x-projection weights live in smem (saves 4 regs)
    {
        float4 v = ((const float4*)Wih0)[tid];
        ((float4*)wih0s)[tid] = v;
    }
    const float bias = par ? (bih1[g] + bhh1[g]) : (bih0[g] + bhh0[g]);

    // ---- init state ----
    if (tid < HH) h0s[tid] = 0.0f;
    else if (tid < 2 * HH) h1s[tid - HH] = 0.0f;
    float c = 0.0f;   // tid<64: c0[tid]; tid in [64,128): c1[tid-64]

    const float* xb = x + (size_t)b * TT * IDIM;

    // prefetch x chunk 0 (XCHUNK*IDIM = 2048 floats; 512 threads x 16B)
    cp_async16(&xbuf[0][tid * 4], xb + tid * 4);
    asm volatile("cp.async.commit_group;\n" ::: "memory");

    const int nchunks = TT / XCHUNK;

    // Iteration t: layer0 step t + layer1 step (t-1)  [pipeline skew]
    for (int t = 0; t < TT; ++t) {
        const int tc  = t & (XCHUNK - 1);
        const int cur = (t / XCHUNK) & 1;
        if (tc == 0) {
            asm volatile("cp.async.wait_group 0;\n" ::: "memory");
            __syncthreads();
            const int nxt = t / XCHUNK + 1;
            if (nxt < nchunks) {
                cp_async16(&xbuf[cur ^ 1][tid * 4],
                           xb + (size_t)nxt * XCHUNK * IDIM + tid * 4);
                asm volatile("cp.async.commit_group;\n" ::: "memory");
            }
        }

        // ---------- phase A: half-dot-products ----------
        ull q0 = 0, q1 = 0;   // layer1: even Wih1@h0, odd Whh1@h1
        ull a0 = 0, a1 = 0;   // layer0 half
        {
            const longlong2* hp1 = (const longlong2*)(par ? h1s : h0s);
#pragma unroll
            for (int i = 0; i < HH / 4; i++) {
                longlong2 v = hp1[i];
                q0 = dfma2(w1[2 * i],     (ull)v.x, q0);
                q1 = dfma2(w1[2 * i + 1], (ull)v.y, q1);
            }
            const longlong2* hp0 = (const longlong2*)h0s + par * (HH / 8);
#pragma unroll
            for (int i = 0; i < HH / 8; i++) {
                longlong2 v = hp0[i];
                a0 = dfma2(w0[2 * i],     (ull)v.x, a0);
                a1 = dfma2(w0[2 * i + 1], (ull)v.y, a1);
            }
            // x term (4 dims each) — weights from smem
            const longlong2* xp = (const longlong2*)&xbuf[cur][tc * IDIM + par * 4];
            const longlong2* wp = (const longlong2*)&wih0s[g * IDIM + par * 4];
            longlong2 xv = xp[0];
            longlong2 wv = wp[0];
            a0 = dfma2((ull)wv.x, (ull)xv.x, a0);
            a1 = dfma2((ull)wv.y, (ull)xv.y, a1);
        }
        float s0 = lo2(a0) + hi2(a0) + lo2(a1) + hi2(a1);
        float s1 = lo2(q0) + hi2(q0) + lo2(q1) + hi2(q1);
        s0 += __shfl_xor_sync(0xffffffffu, s0, 1);
        s1 += __shfl_xor_sync(0xffffffffu, s1, 1);

        // per-gate nonlinearity, in parallel: even thread owns layer0 gate g,
        // odd thread owns layer1 gate g. Gate type warp-uniform -> no divergence.
        {
            const float v  = (par ? s1 : s0) + bias;
            const float tv = (gtype == 2) ? tanh_f(v) : sigf(v);
            (par ? g1t : g0t)[gj * 4 + gtype] = tv;
        }
        __syncthreads();

        // ---------- state phase: one LDS.128 + c update + tanh ----------
        if (tid < HH) {
            float4 G = *(const float4*)&g0t[tid * 4];   // i,f,g,o (transformed)
            c = G.y * c + G.x * G.z;
            h0s[tid] = G.w * tanh_f(c);
        } else if (tid < 2 * HH) {
            if (t > 0) {
                float4 G = *(const float4*)&g1t[(tid - HH) * 4];
                c = G.y * c + G.x * G.z;
                h1s[tid - HH] = G.w * tanh_f(c);
            }
        }
        __syncthreads();
    }

    // ---------- epilogue: layer1 step TT-1 ----------
    {
        ull q0 = 0, q1 = 0;
        const longlong2* hp1 = (const longlong2*)(par ? h1s : h0s);
#pragma unroll
        for (int i = 0; i < HH / 4; i++) {
            longlong2 v = hp1[i];
            q0 = dfma2(w1[2 * i],     (ull)v.x, q0);
            q1 = dfma2(w1[2 * i + 1], (ull)v.y, q1);
        }
        float s1 = lo2(q0) + hi2(q0) + lo2(q1) + hi2(q1);
        s1 += __shfl_xor_sync(0xffffffffu, s1, 1);
        if (par) {
            const float v  = s1 + bias;
            const float tv = (gtype == 2) ? tanh_f(v) : sigf(v);
            g1t[gj * 4 + gtype] = tv;
        }
        __syncthreads();
        if (tid >= HH && tid < 2 * HH) {
            float4 G = *(const float4*)&g1t[(tid - HH) * 4];
            c = G.y * c + G.x * G.z;
            h1s[tid - HH] = G.w * tanh_f(c);
        }
        __syncthreads();
    }

    // ---------- FC head ----------
    if (tid < 32) {
        float part = fcw[tid] * h1s[tid] + fcw[tid + 32] * h1s[tid + 32];
#pragma unroll
        for (int off = 16; off; off >>= 1)
            part += __shfl_xor_sync(0xffffffffu, part, off);
        if (tid == 0) out[b] = sigf(part + fcb[0]);
    }
}

extern "C" void kernel_launch(void* const* d_in, const int* in_sizes, int n_in,
                              void* d_out, int out_size) {
    const float* x    = (const float*)d_in[0];
    const float* Wih0 = (const float*)d_in[1];
    const float* Whh0 = (const float*)d_in[2];
    const float* bih0 = (const float*)d_in[3];
    const float* bhh0 = (const float*)d_in[4];
    const float* Wih1 = (const float*)d_in[5];
    const float* Whh1 = (const float*)d_in[6];
    const float* bih1 = (const float*)d_in[7];
    const float* bhh1 = (const float*)d_in[8];
    const float* fcw  = (const float*)d_in[9];
    const float* fcb  = (const float*)d_in[10];
    float* out = (float*)d_out;

    lstm2_kernel<<<BB, NTHREADS>>>(x, Wih0, Whh0, bih0, bhh0,
                                   Wih1, Whh1, bih1, bhh1, fcw, fcb, out);
}